// round 2
// baseline (speedup 1.0000x reference)
#include <cuda_runtime.h>
#include <math.h>

// DCGRU decoder: SEQ=32, B=1024, N=19, H=128, OUT=1, K=2 (Chebyshev), L=2 layers.
// Reference ignores `inputs` tensor: step input is previous projection (zeros at t=0).

#define BATCH 1024
#define NNODE 19
#define HID   128
#define ROWS  (BATCH * NNODE)   // 19456 = 152 * 128
#define SEQLEN 32

// ---------------- persistent device scratch (no allocations allowed) --------
__device__ float g_h0[ROWS * HID];       // layer0 hidden (B*N, H)
__device__ float g_h1[ROWS * HID];       // layer1 hidden
__device__ float g_X [ROWS * 768];       // gconv feature buffer, row stride 768 (max K)
__device__ float g_ru[ROWS * 256];       // gate output [r | u]
__device__ float g_S2[NNODE * NNODE];    // 2*S@S - I

// ---------------- init kernels ---------------------------------------------
__global__ void k_init_h(const float* __restrict__ ih) {
    int i = blockIdx.x * blockDim.x + threadIdx.x;
    if (i < ROWS * HID) {
        g_h0[i] = ih[i];
        g_h1[i] = ih[ROWS * HID + i];
    }
}

__global__ void k_s2(const float* __restrict__ S) {
    int i = threadIdx.x;
    if (i < NNODE * NNODE) {
        int m = i / NNODE, n = i % NNODE;
        float acc = 0.f;
        for (int k = 0; k < NNODE; k++) acc += S[m * NNODE + k] * S[k * NNODE + n];
        g_S2[i] = 2.f * acc - (m == n ? 1.f : 0.f);
    }
}

// ---------------- fused concat + Chebyshev diffusion ------------------------
// Builds X = [X0 | S@X0 | (2S^2 - I)@X0] into g_X (row stride 768).
// FIN: width of x_in part (1 for layer0, 128 for layer1).
// CAND: multiply h part by r (= g_ru[:, :128]).
// LAYER: which hidden buffer. For LAYER==1, x_in comes from g_h0.
template <int FIN, bool CAND, int LAYER>
__global__ void k_cheby(const float* __restrict__ S, const float* __restrict__ xprev) {
    constexpr int F = FIN + HID;
    __shared__ float s_src[NNODE][F];
    __shared__ float sS[NNODE * NNODE], sS2[NNODE * NNODE];

    const int b = blockIdx.x;
    const int tid = threadIdx.x;

    for (int i = tid; i < NNODE * NNODE; i += 256) { sS[i] = S[i]; sS2[i] = g_S2[i]; }

    for (int i = tid; i < NNODE * F; i += 256) {
        int n = i / F, f = i % F;
        int row = b * NNODE + n;
        float v;
        if (f < FIN) {
            if (FIN == 1) v = xprev ? xprev[row] : 0.f;   // t==0: zeros
            else          v = g_h0[row * HID + f];        // layer1 x_in = new h0
        } else {
            int fh = f - FIN;
            const float* h = LAYER ? g_h1 : g_h0;
            v = h[row * HID + fh];
            if (CAND) v *= g_ru[row * 256 + fh];          // r * h
        }
        s_src[n][f] = v;
    }
    __syncthreads();

    for (int p = tid; p < NNODE * F; p += 256) {
        int f = p % F, m = p / F;
        float x0 = s_src[m][f], a1 = 0.f, a2 = 0.f;
#pragma unroll
        for (int n = 0; n < NNODE; n++) {
            float v = s_src[n][f];
            a1 = fmaf(sS[m * NNODE + n], v, a1);
            a2 = fmaf(sS2[m * NNODE + n], v, a2);
        }
        float* o = g_X + (b * NNODE + m) * 768;
        o[f]         = x0;
        o[F + f]     = a1;
        o[2 * F + f] = a2;
    }
}

// ---------------- GEMM: (19456 x K) @ (K x Nw) + bias + fused epilogue ------
// MODE 0: gate -> g_ru = sigmoid(.)     (Nw = 256)
// MODE 1: cand -> h = u*h + (1-u)*tanh(.)  (Nw = 128)
template <int MODE, int LAYER>
__global__ void __launch_bounds__(256, 2)
k_gemm(const float* __restrict__ W, const float* __restrict__ bias, int K) {
    __shared__ float As[2][8][128];
    __shared__ float Bs[2][8][128];

    const int tid  = threadIdx.x;
    const int row0 = blockIdx.y * 128;
    const int col0 = blockIdx.x * 128;
    const int Nw   = (MODE == 0) ? 256 : 128;

    const int a_row = tid >> 1;            // 0..127
    const int a_kq  = (tid & 1) * 4;       // 0 or 4
    const int b_k   = tid >> 5;            // 0..7
    const int b_c   = (tid & 31) * 4;      // 0..124
    const float* Aptr = g_X + (row0 + a_row) * 768;

    float4 areg, breg;

    auto loadt = [&](int kt) {
        areg = *reinterpret_cast<const float4*>(Aptr + kt + a_kq);
        if (kt + 8 > K) {                  // mask K tail (K=387 case)
            if (kt + a_kq + 0 >= K) areg.x = 0.f;
            if (kt + a_kq + 1 >= K) areg.y = 0.f;
            if (kt + a_kq + 2 >= K) areg.z = 0.f;
            if (kt + a_kq + 3 >= K) areg.w = 0.f;
        }
        if (kt + b_k < K)
            breg = *reinterpret_cast<const float4*>(W + (kt + b_k) * Nw + col0 + b_c);
        else
            breg = make_float4(0.f, 0.f, 0.f, 0.f);
    };
    auto stot = [&](int buf) {
        As[buf][a_kq + 0][a_row] = areg.x;
        As[buf][a_kq + 1][a_row] = areg.y;
        As[buf][a_kq + 2][a_row] = areg.z;
        As[buf][a_kq + 3][a_row] = areg.w;
        *reinterpret_cast<float4*>(&Bs[buf][b_k][b_c]) = breg;
    };

    float acc[8][8];
#pragma unroll
    for (int i = 0; i < 8; i++)
#pragma unroll
        for (int j = 0; j < 8; j++) acc[i][j] = 0.f;

    const int ty = tid >> 4, tx = tid & 15;
    const int ntiles = (K + 7) / 8;

    loadt(0);
    stot(0);
    __syncthreads();

    int cur = 0;
    for (int t = 0; t < ntiles; t++) {
        if (t + 1 < ntiles) loadt((t + 1) * 8);
#pragma unroll
        for (int kk = 0; kk < 8; kk++) {
            float4 a0 = *reinterpret_cast<const float4*>(&As[cur][kk][ty * 8]);
            float4 a1 = *reinterpret_cast<const float4*>(&As[cur][kk][ty * 8 + 4]);
            float4 b0 = *reinterpret_cast<const float4*>(&Bs[cur][kk][tx * 8]);
            float4 b1 = *reinterpret_cast<const float4*>(&Bs[cur][kk][tx * 8 + 4]);
            float av[8] = {a0.x, a0.y, a0.z, a0.w, a1.x, a1.y, a1.z, a1.w};
            float bv[8] = {b0.x, b0.y, b0.z, b0.w, b1.x, b1.y, b1.z, b1.w};
#pragma unroll
            for (int i = 0; i < 8; i++)
#pragma unroll
                for (int j = 0; j < 8; j++)
                    acc[i][j] = fmaf(av[i], bv[j], acc[i][j]);
        }
        if (t + 1 < ntiles) stot(cur ^ 1);
        __syncthreads();
        cur ^= 1;
    }

    // ---------------- epilogue ----------------
    float* hbuf = LAYER ? g_h1 : g_h0;
#pragma unroll
    for (int i = 0; i < 8; i++) {
        int r  = row0 + ty * 8 + i;
        int c0 = col0 + tx * 8;
        if (MODE == 0) {
            float4 o0, o1;
            float* pa = &acc[i][0];
            o0.x = 1.f / (1.f + expf(-(pa[0] + bias[c0 + 0])));
            o0.y = 1.f / (1.f + expf(-(pa[1] + bias[c0 + 1])));
            o0.z = 1.f / (1.f + expf(-(pa[2] + bias[c0 + 2])));
            o0.w = 1.f / (1.f + expf(-(pa[3] + bias[c0 + 3])));
            o1.x = 1.f / (1.f + expf(-(pa[4] + bias[c0 + 4])));
            o1.y = 1.f / (1.f + expf(-(pa[5] + bias[c0 + 5])));
            o1.z = 1.f / (1.f + expf(-(pa[6] + bias[c0 + 6])));
            o1.w = 1.f / (1.f + expf(-(pa[7] + bias[c0 + 7])));
            *reinterpret_cast<float4*>(&g_ru[r * 256 + c0])     = o0;
            *reinterpret_cast<float4*>(&g_ru[r * 256 + c0 + 4]) = o1;
        } else {
            float4 u0 = *reinterpret_cast<const float4*>(&g_ru[r * 256 + 128 + c0]);
            float4 u1 = *reinterpret_cast<const float4*>(&g_ru[r * 256 + 128 + c0 + 4]);
            float4 h0v = *reinterpret_cast<const float4*>(&hbuf[r * HID + c0]);
            float4 h1v = *reinterpret_cast<const float4*>(&hbuf[r * HID + c0 + 4]);
            float* pa = &acc[i][0];
            float4 o0, o1;
            o0.x = u0.x * h0v.x + (1.f - u0.x) * tanhf(pa[0] + bias[c0 + 0]);
            o0.y = u0.y * h0v.y + (1.f - u0.y) * tanhf(pa[1] + bias[c0 + 1]);
            o0.z = u0.z * h0v.z + (1.f - u0.z) * tanhf(pa[2] + bias[c0 + 2]);
            o0.w = u0.w * h0v.w + (1.f - u0.w) * tanhf(pa[3] + bias[c0 + 3]);
            o1.x = u1.x * h1v.x + (1.f - u1.x) * tanhf(pa[4] + bias[c0 + 4]);
            o1.y = u1.y * h1v.y + (1.f - u1.y) * tanhf(pa[5] + bias[c0 + 5]);
            o1.z = u1.z * h1v.z + (1.f - u1.z) * tanhf(pa[6] + bias[c0 + 6]);
            o1.w = u1.w * h1v.w + (1.f - u1.w) * tanhf(pa[7] + bias[c0 + 7]);
            *reinterpret_cast<float4*>(&hbuf[r * HID + c0])     = o0;
            *reinterpret_cast<float4*>(&hbuf[r * HID + c0 + 4]) = o1;
        }
    }
}

// ---------------- projection: out[t, row] = h1[row,:] . Wp + bp -------------
__global__ void k_proj(const float* __restrict__ Wp, const float* __restrict__ bp,
                       float* __restrict__ out_t) {
    int row  = blockIdx.x * 8 + (threadIdx.x >> 5);
    int lane = threadIdx.x & 31;
    const float* hr = g_h1 + row * HID;
    float acc = 0.f;
#pragma unroll
    for (int i = lane; i < HID; i += 32) acc = fmaf(hr[i], Wp[i], acc);
#pragma unroll
    for (int o = 16; o; o >>= 1) acc += __shfl_xor_sync(0xFFFFFFFFu, acc, o);
    if (lane == 0) out_t[row] = acc + bp[0];
}

// ---------------- launch ----------------------------------------------------
extern "C" void kernel_launch(void* const* d_in, const int* in_sizes, int n_in,
                              void* d_out, int out_size) {
    (void)in_sizes; (void)n_in; (void)out_size;
    // metadata order:
    // 0 inputs (UNUSED by reference), 1 initial_hidden_state, 2 support,
    // 3 W_gate0, 4 b_gate0, 5 W_cand0, 6 b_cand0,
    // 7 W_gate1, 8 b_gate1, 9 W_cand1, 10 b_cand1, 11 W_proj, 12 b_proj
    const float* ih  = (const float*)d_in[1];
    const float* S   = (const float*)d_in[2];
    const float* Wg0 = (const float*)d_in[3];
    const float* bg0 = (const float*)d_in[4];
    const float* Wc0 = (const float*)d_in[5];
    const float* bc0 = (const float*)d_in[6];
    const float* Wg1 = (const float*)d_in[7];
    const float* bg1 = (const float*)d_in[8];
    const float* Wc1 = (const float*)d_in[9];
    const float* bc1 = (const float*)d_in[10];
    const float* Wp  = (const float*)d_in[11];
    const float* bp  = (const float*)d_in[12];
    float* out = (float*)d_out;

    k_init_h<<<(ROWS * HID + 255) / 256, 256>>>(ih);
    k_s2<<<1, 384>>>(S);

    const int K0 = 3 * (1 + HID);      // 387
    const int K1 = 3 * (HID + HID);    // 768

    for (int t = 0; t < SEQLEN; t++) {
        const float* xprev = t ? out + (size_t)(t - 1) * ROWS : nullptr;

        // ---- layer 0 ----
        k_cheby<1, false, 0><<<BATCH, 256>>>(S, xprev);
        k_gemm<0, 0><<<dim3(2, 152), 256>>>(Wg0, bg0, K0);
        k_cheby<1, true, 0><<<BATCH, 256>>>(S, xprev);
        k_gemm<1, 0><<<dim3(1, 152), 256>>>(Wc0, bc0, K0);

        // ---- layer 1 (x_in = new h0) ----
        k_cheby<128, false, 1><<<BATCH, 256>>>(S, nullptr);
        k_gemm<0, 1><<<dim3(2, 152), 256>>>(Wg1, bg1, K1);
        k_cheby<128, true, 1><<<BATCH, 256>>>(S, nullptr);
        k_gemm<1, 1><<<dim3(1, 152), 256>>>(Wc1, bc1, K1);

        // ---- projection (also the next step's input) ----
        k_proj<<<ROWS / 8, 256>>>(Wp, bp, out + (size_t)t * ROWS);
    }
}

// round 3
// speedup vs baseline: 1.0815x; 1.0815x over previous
#include <cuda_runtime.h>
#include <math.h>

// DCGRU decoder: SEQ=32, B=1024, N=19, H=128, OUT=1, K=2 (Chebyshev), L=2 layers.
// Reference ignores `inputs`: step input is previous projection (zeros at t=0).
// R3: GEMMs on tensor cores via 3xTF32 split (fp32-class accuracy).

#define BATCH 1024
#define NNODE 19
#define HID   128
#define ROWS  (BATCH * NNODE)   // 19456 = 152 * 128
#define SEQLEN 32

#define KP0 416                 // 387 padded to multiple of 32
#define KP1 768

// W buffer offsets: [hi plane | lo plane] per matrix, zero-padded rows
#define OFF_G0 0
#define OFF_C0 (OFF_G0 + 2 * KP0 * 256)
#define OFF_G1 (OFF_C0 + 2 * KP0 * 128)
#define OFF_C1 (OFF_G1 + 2 * KP1 * 256)
#define WTOT   (OFF_C1 + 2 * KP1 * 128)

// ---------------- persistent device scratch ---------------------------------
__device__ float g_h0[ROWS * HID];
__device__ float g_h1[ROWS * HID];
__device__ float g_X0[ROWS * KP0];     // layer0 features, stride 416, pad zeros
__device__ float g_X1[ROWS * KP1];     // layer1 features, stride 768
__device__ float g_ru[ROWS * 256];     // gate output [r | u]
__device__ float g_S2[NNODE * NNODE];
__device__ float g_W [WTOT];           // tf32-bit-pattern weights, hi/lo planes

__device__ __forceinline__ unsigned f2tf(float x) {
    unsigned u; asm("cvt.rna.tf32.f32 %0, %1;" : "=r"(u) : "f"(x)); return u;
}

// ---------------- init kernels ----------------------------------------------
__global__ void k_init_h(const float* __restrict__ ih) {
    int i = blockIdx.x * blockDim.x + threadIdx.x;
    if (i < ROWS * HID) { g_h0[i] = ih[i]; g_h1[i] = ih[ROWS * HID + i]; }
}

__global__ void k_zero_x0() {
    int i = blockIdx.x * blockDim.x + threadIdx.x;
    if (i < ROWS * KP0) g_X0[i] = 0.f;
}

__global__ void k_s2(const float* __restrict__ S) {
    int i = threadIdx.x;
    if (i < NNODE * NNODE) {
        int m = i / NNODE, n = i % NNODE;
        float acc = 0.f;
        for (int k = 0; k < NNODE; k++) acc += S[m * NNODE + k] * S[k * NNODE + n];
        g_S2[i] = 2.f * acc - (m == n ? 1.f : 0.f);
    }
}

// Split W into tf32 hi/lo planes, zero-padded to Kp rows.
__global__ void k_prepw(const float* __restrict__ W, int off, int K, int Kp, int Nw) {
    int i = blockIdx.x * blockDim.x + threadIdx.x;
    if (i >= Kp * Nw) return;
    int k = i / Nw, n = i % Nw;
    float w = (k < K) ? W[k * Nw + n] : 0.f;
    unsigned h = f2tf(w);
    float hf = __uint_as_float(h);
    unsigned l = f2tf(w - hf);
    g_W[off + i] = hf;
    g_W[off + Kp * Nw + i] = __uint_as_float(l);
}

// ---------------- fused concat + Chebyshev diffusion -------------------------
// X = [X0 | S@X0 | (2S^2-I)@X0] -> g_X0 (stride 416) or g_X1 (stride 768)
template <int FIN, bool CAND, int LAYER>
__global__ void k_cheby(const float* __restrict__ S, const float* __restrict__ xprev) {
    constexpr int F = FIN + HID;
    constexpr int STR = LAYER ? KP1 : KP0;
    __shared__ float s_src[NNODE][F];
    __shared__ float sS[NNODE * NNODE], sS2[NNODE * NNODE];

    const int b = blockIdx.x;
    const int tid = threadIdx.x;
    float* Xout = LAYER ? g_X1 : g_X0;

    for (int i = tid; i < NNODE * NNODE; i += 256) { sS[i] = S[i]; sS2[i] = g_S2[i]; }

    for (int i = tid; i < NNODE * F; i += 256) {
        int n = i / F, f = i % F;
        int row = b * NNODE + n;
        float v;
        if (f < FIN) {
            if (FIN == 1) v = xprev ? xprev[row] : 0.f;
            else          v = g_h0[row * HID + f];
        } else {
            int fh = f - FIN;
            const float* h = LAYER ? g_h1 : g_h0;
            v = h[row * HID + fh];
            if (CAND) v *= g_ru[row * 256 + fh];
        }
        s_src[n][f] = v;
    }
    __syncthreads();

    for (int p = tid; p < NNODE * F; p += 256) {
        int f = p % F, m = p / F;
        float x0 = s_src[m][f], a1 = 0.f, a2 = 0.f;
#pragma unroll
        for (int n = 0; n < NNODE; n++) {
            float v = s_src[n][f];
            a1 = fmaf(sS[m * NNODE + n], v, a1);
            a2 = fmaf(sS2[m * NNODE + n], v, a2);
        }
        float* o = Xout + (size_t)(b * NNODE + m) * STR;
        o[f]         = x0;
        o[F + f]     = a1;
        o[2 * F + f] = a2;
    }
}

// ---------------- tensor-core GEMM (3xTF32) ----------------------------------
// C = X @ W + bias, fused epilogue. BM=128, BN=128, BK=32. 8 warps of 32x64.
// MODE 0: g_ru = sigmoid(.)   MODE 1: h = u*h + (1-u)*tanh(.)
#define AS_LD 132
#define PLANE (32 * AS_LD)

#define MMA3(acc, ah, al, bh0, bh1, bl0, bl1)                                   \
    asm volatile("mma.sync.aligned.m16n8k8.row.col.f32.tf32.tf32.f32 "          \
        "{%0,%1,%2,%3},{%4,%5,%6,%7},{%8,%9},{%0,%1,%2,%3};"                    \
        : "+f"(acc[0]), "+f"(acc[1]), "+f"(acc[2]), "+f"(acc[3])                \
        : "r"(ah[0]), "r"(ah[1]), "r"(ah[2]), "r"(ah[3]), "r"(bh0), "r"(bh1));  \
    asm volatile("mma.sync.aligned.m16n8k8.row.col.f32.tf32.tf32.f32 "          \
        "{%0,%1,%2,%3},{%4,%5,%6,%7},{%8,%9},{%0,%1,%2,%3};"                    \
        : "+f"(acc[0]), "+f"(acc[1]), "+f"(acc[2]), "+f"(acc[3])                \
        : "r"(ah[0]), "r"(ah[1]), "r"(ah[2]), "r"(ah[3]), "r"(bl0), "r"(bl1));  \
    asm volatile("mma.sync.aligned.m16n8k8.row.col.f32.tf32.tf32.f32 "          \
        "{%0,%1,%2,%3},{%4,%5,%6,%7},{%8,%9},{%0,%1,%2,%3};"                    \
        : "+f"(acc[0]), "+f"(acc[1]), "+f"(acc[2]), "+f"(acc[3])                \
        : "r"(al[0]), "r"(al[1]), "r"(al[2]), "r"(al[3]), "r"(bh0), "r"(bh1));

template <int MODE, int LAYER>
__global__ void __launch_bounds__(256)
k_gemm(const float* __restrict__ bias, int woff, int Kp) {
    extern __shared__ float sm[];
    float* As  = sm;               // [32][132], A k-major
    float* Bsh = sm + PLANE;       // [32][132], W hi (tf32 bits)
    float* Bsl = sm + 2 * PLANE;   // [32][132], W lo

    const int Nw = (MODE == 0) ? 256 : 128;
    const int strideX = LAYER ? KP1 : KP0;
    const float* Xbuf = LAYER ? g_X1 : g_X0;
    const float* Wh = g_W + woff;
    const float* Wl = Wh + Kp * Nw;

    const int tid = threadIdx.x;
    const int row0 = blockIdx.y * 128, col0 = blockIdx.x * 128;
    const int wid = tid >> 5, lane = tid & 31;
    const int wm = (wid & 3) * 32, wn = (wid >> 2) * 64;
    const int gr = lane >> 2, gc = lane & 3;

    const int m_ld = tid >> 1, k0_ld = (tid & 1) * 16;  // A: row, k-quarter
    const int kb = tid >> 3, qb = tid & 7;              // B: k-row, col-eighth

    float4 pa[4], pbh[4], pbl[4];
    float acc[2][8][4];
#pragma unroll
    for (int i = 0; i < 2; i++)
#pragma unroll
        for (int j = 0; j < 8; j++)
#pragma unroll
            for (int q = 0; q < 4; q++) acc[i][j][q] = 0.f;

    const int nt = Kp / 32;

    auto g2r = [&](int kt) {
        const float* Ap = Xbuf + (size_t)(row0 + m_ld) * strideX + kt * 32 + k0_ld;
#pragma unroll
        for (int i = 0; i < 4; i++) pa[i] = *(const float4*)(Ap + 4 * i);
        const float* Bph = Wh + (size_t)(kt * 32 + kb) * Nw + col0 + qb * 16;
        const float* Bpl = Wl + (size_t)(kt * 32 + kb) * Nw + col0 + qb * 16;
#pragma unroll
        for (int j = 0; j < 4; j++) { pbh[j] = *(const float4*)(Bph + 4 * j);
                                      pbl[j] = *(const float4*)(Bpl + 4 * j); }
    };
    auto r2s = [&]() {
#pragma unroll
        for (int i = 0; i < 4; i++) {
            As[(k0_ld + 4 * i + 0) * AS_LD + m_ld] = pa[i].x;
            As[(k0_ld + 4 * i + 1) * AS_LD + m_ld] = pa[i].y;
            As[(k0_ld + 4 * i + 2) * AS_LD + m_ld] = pa[i].z;
            As[(k0_ld + 4 * i + 3) * AS_LD + m_ld] = pa[i].w;
        }
#pragma unroll
        for (int j = 0; j < 4; j++) {
            *(float4*)(&Bsh[kb * AS_LD + qb * 16 + 4 * j]) = pbh[j];
            *(float4*)(&Bsl[kb * AS_LD + qb * 16 + 4 * j]) = pbl[j];
        }
    };

    g2r(0);
    for (int kt = 0; kt < nt; kt++) {
        __syncthreads();
        r2s();
        __syncthreads();
        if (kt + 1 < nt) g2r(kt + 1);
#pragma unroll
        for (int ks = 0; ks < 32; ks += 8) {
            unsigned ah[2][4], al[2][4];
#pragma unroll
            for (int mi = 0; mi < 2; mi++) {
                int mb = wm + mi * 16 + gr;
                float a0 = As[(ks + gc) * AS_LD + mb];
                float a1 = As[(ks + gc) * AS_LD + mb + 8];
                float a2 = As[(ks + 4 + gc) * AS_LD + mb];
                float a3 = As[(ks + 4 + gc) * AS_LD + mb + 8];
                ah[mi][0] = f2tf(a0); al[mi][0] = f2tf(a0 - __uint_as_float(ah[mi][0]));
                ah[mi][1] = f2tf(a1); al[mi][1] = f2tf(a1 - __uint_as_float(ah[mi][1]));
                ah[mi][2] = f2tf(a2); al[mi][2] = f2tf(a2 - __uint_as_float(ah[mi][2]));
                ah[mi][3] = f2tf(a3); al[mi][3] = f2tf(a3 - __uint_as_float(ah[mi][3]));
            }
#pragma unroll
            for (int ni = 0; ni < 8; ni++) {
                int nb = wn + ni * 8 + gr;
                unsigned bh0 = __float_as_uint(Bsh[(ks + gc) * AS_LD + nb]);
                unsigned bh1 = __float_as_uint(Bsh[(ks + 4 + gc) * AS_LD + nb]);
                unsigned bl0 = __float_as_uint(Bsl[(ks + gc) * AS_LD + nb]);
                unsigned bl1 = __float_as_uint(Bsl[(ks + 4 + gc) * AS_LD + nb]);
                MMA3(acc[0][ni], ah[0], al[0], bh0, bh1, bl0, bl1);
                MMA3(acc[1][ni], ah[1], al[1], bh0, bh1, bl0, bl1);
            }
        }
    }

    // ---------------- epilogue ----------------
    float* hbuf = LAYER ? g_h1 : g_h0;
#pragma unroll
    for (int mi = 0; mi < 2; mi++) {
#pragma unroll
        for (int ni = 0; ni < 8; ni++) {
            int r0 = row0 + wm + mi * 16 + gr;
            int c  = col0 + wn + ni * 8 + gc * 2;
            float b0 = bias[c], b1 = bias[c + 1];
            float* pa = acc[mi][ni];
            if (MODE == 0) {
                float2 v0, v1;
                v0.x = 1.f / (1.f + expf(-(pa[0] + b0)));
                v0.y = 1.f / (1.f + expf(-(pa[1] + b1)));
                v1.x = 1.f / (1.f + expf(-(pa[2] + b0)));
                v1.y = 1.f / (1.f + expf(-(pa[3] + b1)));
                *(float2*)(&g_ru[(size_t)r0 * 256 + c])       = v0;
                *(float2*)(&g_ru[(size_t)(r0 + 8) * 256 + c]) = v1;
            } else {
#pragma unroll
                for (int rr = 0; rr < 2; rr++) {
                    int r = r0 + rr * 8;
                    float2 u = *(const float2*)(&g_ru[(size_t)r * 256 + 128 + c]);
                    float2 h = *(const float2*)(&hbuf[(size_t)r * HID + c]);
                    float2 o;
                    o.x = u.x * h.x + (1.f - u.x) * tanhf(pa[rr * 2 + 0] + b0);
                    o.y = u.y * h.y + (1.f - u.y) * tanhf(pa[rr * 2 + 1] + b1);
                    *(float2*)(&hbuf[(size_t)r * HID + c]) = o;
                }
            }
        }
    }
}

// ---------------- projection -------------------------------------------------
__global__ void k_proj(const float* __restrict__ Wp, const float* __restrict__ bp,
                       float* __restrict__ out_t) {
    int row  = blockIdx.x * 8 + (threadIdx.x >> 5);
    int lane = threadIdx.x & 31;
    const float* hr = g_h1 + (size_t)row * HID;
    float acc = 0.f;
#pragma unroll
    for (int i = lane; i < HID; i += 32) acc = fmaf(hr[i], Wp[i], acc);
#pragma unroll
    for (int o = 16; o; o >>= 1) acc += __shfl_xor_sync(0xFFFFFFFFu, acc, o);
    if (lane == 0) out_t[row] = acc + bp[0];
}

// ---------------- launch -----------------------------------------------------
extern "C" void kernel_launch(void* const* d_in, const int* in_sizes, int n_in,
                              void* d_out, int out_size) {
    (void)in_sizes; (void)n_in; (void)out_size;
    const float* ih  = (const float*)d_in[1];
    const float* S   = (const float*)d_in[2];
    const float* Wg0 = (const float*)d_in[3];
    const float* bg0 = (const float*)d_in[4];
    const float* Wc0 = (const float*)d_in[5];
    const float* bc0 = (const float*)d_in[6];
    const float* Wg1 = (const float*)d_in[7];
    const float* bg1 = (const float*)d_in[8];
    const float* Wc1 = (const float*)d_in[9];
    const float* bc1 = (const float*)d_in[10];
    const float* Wp  = (const float*)d_in[11];
    const float* bp  = (const float*)d_in[12];
    float* out = (float*)d_out;

    const int SMEM = 3 * PLANE * (int)sizeof(float);  // 50688
    cudaFuncSetAttribute((const void*)k_gemm<0, 0>, cudaFuncAttributeMaxDynamicSharedMemorySize, SMEM);
    cudaFuncSetAttribute((const void*)k_gemm<1, 0>, cudaFuncAttributeMaxDynamicSharedMemorySize, SMEM);
    cudaFuncSetAttribute((const void*)k_gemm<0, 1>, cudaFuncAttributeMaxDynamicSharedMemorySize, SMEM);
    cudaFuncSetAttribute((const void*)k_gemm<1, 1>, cudaFuncAttributeMaxDynamicSharedMemorySize, SMEM);

    k_init_h<<<(ROWS * HID + 255) / 256, 256>>>(ih);
    k_zero_x0<<<(ROWS * KP0 + 255) / 256, 256>>>();
    k_s2<<<1, 384>>>(S);
    k_prepw<<<(KP0 * 256 + 255) / 256, 256>>>(Wg0, OFF_G0, 387, KP0, 256);
    k_prepw<<<(KP0 * 128 + 255) / 256, 256>>>(Wc0, OFF_C0, 387, KP0, 128);
    k_prepw<<<(KP1 * 256 + 255) / 256, 256>>>(Wg1, OFF_G1, 768, KP1, 256);
    k_prepw<<<(KP1 * 128 + 255) / 256, 256>>>(Wc1, OFF_C1, 768, KP1, 128);

    for (int t = 0; t < SEQLEN; t++) {
        const float* xprev = t ? out + (size_t)(t - 1) * ROWS : nullptr;

        k_cheby<1, false, 0><<<BATCH, 256>>>(S, xprev);
        k_gemm<0, 0><<<dim3(2, 152), 256, SMEM>>>(bg0, OFF_G0, KP0);
        k_cheby<1, true, 0><<<BATCH, 256>>>(S, xprev);
        k_gemm<1, 0><<<dim3(1, 152), 256, SMEM>>>(bc0, OFF_C0, KP0);

        k_cheby<128, false, 1><<<BATCH, 256>>>(S, nullptr);
        k_gemm<0, 1><<<dim3(2, 152), 256, SMEM>>>(bg1, OFF_G1, KP1);
        k_cheby<128, true, 1><<<BATCH, 256>>>(S, nullptr);
        k_gemm<1, 1><<<dim3(1, 152), 256, SMEM>>>(bc1, OFF_C1, KP1);

        k_proj<<<ROWS / 8, 256>>>(Wp, bp, out + (size_t)t * ROWS);
    }
}

// round 5
// speedup vs baseline: 1.8162x; 1.6793x over previous
#include <cuda_runtime.h>
#include <cuda_bf16.h>
#include <math.h>
#include <stdint.h>

// DCGRU decoder: SEQ=32, B=1024, N=19, H=128, OUT=1, K=2 Chebyshev, 2 layers.
// R5: mma.sync bf16 (3-pass hi/lo split) + ldmatrix + cp.async double buffer.
// (tcgen05 unusable: harness PTX targets sm_103 without the 'a' feature suffix.)

#define BATCH 1024
#define NNODE 19
#define HID   128
#define ROWS  (BATCH * NNODE)   // 19456 = 152 * 128
#define SEQLEN 32

#define KP0 448                  // 387 padded to mult of 32
#define K0R 387
#define KP1 768

// weight plane offsets (bf16 elements), stored transposed: [Nw][KP]
#define WO_G0 0
#define WO_C0 (WO_G0 + 256 * KP0)
#define WO_G1 (WO_C0 + 128 * KP0)
#define WO_C1 (WO_G1 + 256 * KP1)
#define WTOT  (WO_C1 + 128 * KP1)

// ---------------- persistent device scratch ---------------------------------
__device__ float g_h0[ROWS * HID];
__device__ float g_h1[ROWS * HID];
__device__ float g_ru[ROWS * 256];
__device__ float g_S2[NNODE * NNODE];
__device__ __align__(16) __nv_bfloat16 g_X0h[ROWS * KP0];
__device__ __align__(16) __nv_bfloat16 g_X0l[ROWS * KP0];
__device__ __align__(16) __nv_bfloat16 g_X1h[ROWS * KP1];
__device__ __align__(16) __nv_bfloat16 g_X1l[ROWS * KP1];
__device__ __align__(16) __nv_bfloat16 g_Wh[WTOT];
__device__ __align__(16) __nv_bfloat16 g_Wl[WTOT];

// ---------------- helpers ----------------------------------------------------
__device__ __forceinline__ uint32_t smem_u32(const void* p) {
    uint32_t a;
    asm("{ .reg .u64 t; cvta.to.shared.u64 t, %1; cvt.u32.u64 %0, t; }" : "=r"(a) : "l"(p));
    return a;
}
__device__ __forceinline__ void cpasync16(uint32_t dst, const void* src) {
    asm volatile("cp.async.cg.shared.global [%0], [%1], 16;" :: "r"(dst), "l"(src) : "memory");
}
#define CP_COMMIT() asm volatile("cp.async.commit_group;" ::: "memory")
#define CP_WAIT(n)  asm volatile("cp.async.wait_group %0;" :: "n"(n) : "memory")

__device__ __forceinline__ void ldsm_x4(uint32_t* r, uint32_t addr) {
    asm volatile("ldmatrix.sync.aligned.m8n8.x4.shared.b16 {%0,%1,%2,%3}, [%4];"
                 : "=r"(r[0]), "=r"(r[1]), "=r"(r[2]), "=r"(r[3]) : "r"(addr));
}
__device__ __forceinline__ void mma_bf16(float* d, const uint32_t* a, const uint32_t* b) {
    asm volatile("mma.sync.aligned.m16n8k16.row.col.f32.bf16.bf16.f32 "
                 "{%0,%1,%2,%3},{%4,%5,%6,%7},{%8,%9},{%0,%1,%2,%3};"
                 : "+f"(d[0]), "+f"(d[1]), "+f"(d[2]), "+f"(d[3])
                 : "r"(a[0]), "r"(a[1]), "r"(a[2]), "r"(a[3]), "r"(b[0]), "r"(b[1]));
}
__device__ __forceinline__ void sthl(__nv_bfloat16* H, __nv_bfloat16* L, size_t i, float v) {
    __nv_bfloat16 h = __float2bfloat16(v);
    H[i] = h;
    L[i] = __float2bfloat16(v - __bfloat162float(h));
}

// ---------------- init kernels -----------------------------------------------
__global__ void k_init_h(const float* __restrict__ ih) {
    int i = blockIdx.x * blockDim.x + threadIdx.x;
    if (i < ROWS * HID) { g_h0[i] = ih[i]; g_h1[i] = ih[ROWS * HID + i]; }
}
__global__ void k_zpad() {   // zero X0 K-pad cols [387,448)
    int i = blockIdx.x * blockDim.x + threadIdx.x;
    if (i < ROWS * (KP0 - K0R)) {
        int row = i / (KP0 - K0R), c = K0R + i % (KP0 - K0R);
        g_X0h[(size_t)row * KP0 + c] = __float2bfloat16(0.f);
        g_X0l[(size_t)row * KP0 + c] = __float2bfloat16(0.f);
    }
}
__global__ void k_s2(const float* __restrict__ S) {
    int i = threadIdx.x;
    if (i < NNODE * NNODE) {
        int m = i / NNODE, n = i % NNODE;
        float acc = 0.f;
        for (int k = 0; k < NNODE; k++) acc += S[m * NNODE + k] * S[k * NNODE + n];
        g_S2[i] = 2.f * acc - (m == n ? 1.f : 0.f);
    }
}
// transpose + split weights: plane[off + n*KP + k] = split(W[k*Nw+n])
__global__ void k_prepw(const float* __restrict__ W, int off, int K, int KP_, int Nw) {
    int i = blockIdx.x * blockDim.x + threadIdx.x;
    if (i >= Nw * KP_) return;
    int n = i / KP_, k = i % KP_;
    float w = (k < K) ? W[k * Nw + n] : 0.f;
    __nv_bfloat16 h = __float2bfloat16(w);
    g_Wh[off + i] = h;
    g_Wl[off + i] = __float2bfloat16(w - __bfloat162float(h));
}

// ---------------- fused concat + Chebyshev -> bf16 hi/lo planes --------------
template <int FIN, bool CAND, int LAYER>
__global__ void k_cheby(const float* __restrict__ S, const float* __restrict__ xprev) {
    constexpr int F = FIN + HID;
    constexpr int STR = LAYER ? KP1 : KP0;
    __shared__ float s_src[NNODE][F];
    __shared__ float sS[NNODE * NNODE], sS2[NNODE * NNODE];

    const int b = blockIdx.x, tid = threadIdx.x;
    __nv_bfloat16* Xh = LAYER ? g_X1h : g_X0h;
    __nv_bfloat16* Xl = LAYER ? g_X1l : g_X0l;

    for (int i = tid; i < NNODE * NNODE; i += 256) { sS[i] = S[i]; sS2[i] = g_S2[i]; }

    for (int i = tid; i < NNODE * F; i += 256) {
        int n = i / F, f = i % F;
        int row = b * NNODE + n;
        float v;
        if (f < FIN) {
            if (FIN == 1) v = xprev ? xprev[row] : 0.f;
            else          v = g_h0[(size_t)row * HID + f];
        } else {
            int fh = f - FIN;
            const float* h = LAYER ? g_h1 : g_h0;
            v = h[(size_t)row * HID + fh];
            if (CAND) v *= g_ru[(size_t)row * 256 + fh];
        }
        s_src[n][f] = v;
    }
    __syncthreads();

    for (int p = tid; p < NNODE * F; p += 256) {
        int f = p % F, m = p / F;
        float x0 = s_src[m][f], a1 = 0.f, a2 = 0.f;
#pragma unroll
        for (int n = 0; n < NNODE; n++) {
            float v = s_src[n][f];
            a1 = fmaf(sS[m * NNODE + n], v, a1);
            a2 = fmaf(sS2[m * NNODE + n], v, a2);
        }
        size_t base = (size_t)(b * NNODE + m) * STR;
        sthl(Xh, Xl, base + f,         x0);
        sthl(Xh, Xl, base + F + f,     a1);
        sthl(Xh, Xl, base + 2 * F + f, a2);
    }
}

// ---------------- bf16 mma.sync GEMM -----------------------------------------
// BM=128, BN=128, BK=32. 8 warps: warp grid 4(m) x 2(n), warp tile 32x64.
// Smem rows padded to 40 halves (80B): conflict-free LDSM.
// MODE 0 (gate): g_ru = sigmoid(.)   MODE 1 (cand): h = u*h + (1-u)*tanh(.)
#define RPAD 40
#define PLANEH (128 * RPAD)                 // halves per plane
#define STAGEB (4 * PLANEH * 2)             // bytes per stage (Ah,Al,Bh,Bl)

template <int MODE, int LAYER>
__global__ void __launch_bounds__(256)
k_gemm(const float* __restrict__ bias) {
    constexpr int NW = (MODE == 0) ? 256 : 128;
    constexpr int KP = LAYER ? KP1 : KP0;
    constexpr int NT = KP / 32;

    extern __shared__ __align__(16) char smem[];
    const uint32_t sbase = smem_u32(smem);

    const int tid = threadIdx.x, wid = tid >> 5, lane = tid & 31;
    const int row0 = blockIdx.x * 128;
    const int col0 = blockIdx.y * 128;
    const int wm = (wid & 3) * 32, wn = (wid >> 2) * 64;
    const int gr = lane >> 2, gc = lane & 3;

    const __nv_bfloat16* Xh = LAYER ? g_X1h : g_X0h;
    const __nv_bfloat16* Xl = LAYER ? g_X1l : g_X0l;
    const int woff = (MODE == 0) ? (LAYER ? WO_G1 : WO_G0) : (LAYER ? WO_C1 : WO_C0);
    const __nv_bfloat16* Wh = g_Wh + woff;
    const __nv_bfloat16* Wl = g_Wl + woff;

    // loader mapping: 2048 16B chunks / 256 threads = 8 per thread
    const int l_row = (tid * 4 + 0) >> 2;        // chunk layout derived below
    (void)l_row;

    auto load_stage = [&](int kt, int s) {
        const uint32_t stg = sbase + s * STAGEB;
#pragma unroll
        for (int i = 0; i < 8; i++) {
            int slot = tid + i * 256;            // 0..2047
            int pl   = slot >> 9;                // 0..3 : Ah, Al, Bh, Bl
            int e    = slot & 511;
            int r    = e >> 2;                   // 0..127
            int kq   = (e & 3) * 8;              // 0,8,16,24
            uint32_t dst = stg + (uint32_t)pl * (PLANEH * 2) + (uint32_t)(r * RPAD + kq) * 2;
            const __nv_bfloat16* src;
            if (pl == 0)      src = Xh + (size_t)(row0 + r) * KP + kt * 32 + kq;
            else if (pl == 1) src = Xl + (size_t)(row0 + r) * KP + kt * 32 + kq;
            else if (pl == 2) src = Wh + (size_t)(col0 + r) * KP + kt * 32 + kq;
            else              src = Wl + (size_t)(col0 + r) * KP + kt * 32 + kq;
            cpasync16(dst, src);
        }
        CP_COMMIT();
    };

    float acc[2][8][4];
#pragma unroll
    for (int i = 0; i < 2; i++)
#pragma unroll
        for (int j = 0; j < 8; j++)
#pragma unroll
            for (int q = 0; q < 4; q++) acc[i][j][q] = 0.f;

    load_stage(0, 0);

    // lane addressing for LDSM
    const int a_r  = lane & 15, a_k = (lane >> 4) * 8;                   // A x4
    const int b_r  = (lane & 7) + ((lane >> 4) << 3), b_k = ((lane >> 3) & 1) * 8;  // B x4

    for (int kt = 0; kt < NT; kt++) {
        const int s = kt & 1;
        if (kt + 1 < NT) load_stage(kt + 1, s ^ 1);
        if (kt + 1 < NT) { CP_WAIT(1); } else { CP_WAIT(0); }
        __syncthreads();

        const uint32_t stg = sbase + s * STAGEB;
        const uint32_t sAh = stg;
        const uint32_t sAl = stg + PLANEH * 2;
        const uint32_t sBh = stg + 2 * PLANEH * 2;
        const uint32_t sBl = stg + 3 * PLANEH * 2;

#pragma unroll
        for (int ks = 0; ks < 32; ks += 16) {
            uint32_t ah[2][4], al[2][4], bh[4][4], bl[4][4];
#pragma unroll
            for (int mi = 0; mi < 2; mi++) {
                uint32_t off = (uint32_t)((wm + mi * 16 + a_r) * RPAD + ks + a_k) * 2;
                ldsm_x4(ah[mi], sAh + off);
                ldsm_x4(al[mi], sAl + off);
            }
#pragma unroll
            for (int nq = 0; nq < 4; nq++) {   // 4 x (two n8 tiles) = 64 cols
                uint32_t off = (uint32_t)((wn + nq * 16 + b_r) * RPAD + ks + b_k) * 2;
                ldsm_x4(bh[nq], sBh + off);
                ldsm_x4(bl[nq], sBl + off);
            }
#pragma unroll
            for (int nq = 0; nq < 4; nq++) {
#pragma unroll
                for (int half = 0; half < 2; half++) {
                    int ni = nq * 2 + half;
                    const uint32_t* pbh = &bh[nq][half * 2];
                    const uint32_t* pbl = &bl[nq][half * 2];
#pragma unroll
                    for (int mi = 0; mi < 2; mi++) {
                        mma_bf16(acc[mi][ni], ah[mi], pbh);   // Ah*Bh
                        mma_bf16(acc[mi][ni], al[mi], pbh);   // Al*Bh
                        mma_bf16(acc[mi][ni], ah[mi], pbl);   // Ah*Bl
                    }
                }
            }
        }
        __syncthreads();
    }

    // ---------------- epilogue ----------------
    float* hbuf = LAYER ? g_h1 : g_h0;
#pragma unroll
    for (int mi = 0; mi < 2; mi++) {
#pragma unroll
        for (int ni = 0; ni < 8; ni++) {
            int r0 = row0 + wm + mi * 16 + gr;
            int c  = col0 + wn + ni * 8 + gc * 2;
            float b0 = bias[c], b1 = bias[c + 1];
            float* pa = acc[mi][ni];
            if (MODE == 0) {
                float2 v0, v1;
                v0.x = 1.f / (1.f + expf(-(pa[0] + b0)));
                v0.y = 1.f / (1.f + expf(-(pa[1] + b1)));
                v1.x = 1.f / (1.f + expf(-(pa[2] + b0)));
                v1.y = 1.f / (1.f + expf(-(pa[3] + b1)));
                *(float2*)(&g_ru[(size_t)r0 * 256 + c])       = v0;
                *(float2*)(&g_ru[(size_t)(r0 + 8) * 256 + c]) = v1;
            } else {
#pragma unroll
                for (int rr = 0; rr < 2; rr++) {
                    int r = r0 + rr * 8;
                    float2 u = *(const float2*)(&g_ru[(size_t)r * 256 + 128 + c]);
                    float2 h = *(const float2*)(&hbuf[(size_t)r * HID + c]);
                    float2 o;
                    o.x = u.x * h.x + (1.f - u.x) * tanhf(pa[rr * 2 + 0] + b0);
                    o.y = u.y * h.y + (1.f - u.y) * tanhf(pa[rr * 2 + 1] + b1);
                    *(float2*)(&hbuf[(size_t)r * HID + c]) = o;
                }
            }
        }
    }
}

// ---------------- projection -------------------------------------------------
__global__ void k_proj(const float* __restrict__ Wp, const float* __restrict__ bp,
                       float* __restrict__ out_t) {
    int row  = blockIdx.x * 8 + (threadIdx.x >> 5);
    int lane = threadIdx.x & 31;
    const float* hr = g_h1 + (size_t)row * HID;
    float acc = 0.f;
#pragma unroll
    for (int i = lane; i < HID; i += 32) acc = fmaf(hr[i], Wp[i], acc);
#pragma unroll
    for (int o = 16; o; o >>= 1) acc += __shfl_xor_sync(0xFFFFFFFFu, acc, o);
    if (lane == 0) out_t[row] = acc + bp[0];
}

// ---------------- launch -----------------------------------------------------
extern "C" void kernel_launch(void* const* d_in, const int* in_sizes, int n_in,
                              void* d_out, int out_size) {
    (void)in_sizes; (void)n_in; (void)out_size;
    const float* ih  = (const float*)d_in[1];
    const float* S   = (const float*)d_in[2];
    const float* Wg0 = (const float*)d_in[3];
    const float* bg0 = (const float*)d_in[4];
    const float* Wc0 = (const float*)d_in[5];
    const float* bc0 = (const float*)d_in[6];
    const float* Wg1 = (const float*)d_in[7];
    const float* bg1 = (const float*)d_in[8];
    const float* Wc1 = (const float*)d_in[9];
    const float* bc1 = (const float*)d_in[10];
    const float* Wp  = (const float*)d_in[11];
    const float* bp  = (const float*)d_in[12];
    float* out = (float*)d_out;

    const int SMEM = 2 * STAGEB;   // 81920 B
    cudaFuncSetAttribute((const void*)k_gemm<0, 0>, cudaFuncAttributeMaxDynamicSharedMemorySize, SMEM);
    cudaFuncSetAttribute((const void*)k_gemm<0, 1>, cudaFuncAttributeMaxDynamicSharedMemorySize, SMEM);
    cudaFuncSetAttribute((const void*)k_gemm<1, 0>, cudaFuncAttributeMaxDynamicSharedMemorySize, SMEM);
    cudaFuncSetAttribute((const void*)k_gemm<1, 1>, cudaFuncAttributeMaxDynamicSharedMemorySize, SMEM);

    k_init_h<<<(ROWS * HID + 255) / 256, 256>>>(ih);
    k_zpad<<<(ROWS * (KP0 - K0R) + 255) / 256, 256>>>();
    k_s2<<<1, 384>>>(S);
    k_prepw<<<(256 * KP0 + 255) / 256, 256>>>(Wg0, WO_G0, K0R, KP0, 256);
    k_prepw<<<(128 * KP0 + 255) / 256, 256>>>(Wc0, WO_C0, K0R, KP0, 128);
    k_prepw<<<(256 * KP1 + 255) / 256, 256>>>(Wg1, WO_G1, 768, KP1, 256);
    k_prepw<<<(128 * KP1 + 255) / 256, 256>>>(Wc1, WO_C1, 768, KP1, 128);

    for (int t = 0; t < SEQLEN; t++) {
        const float* xprev = t ? out + (size_t)(t - 1) * ROWS : nullptr;

        k_cheby<1, false, 0><<<BATCH, 256>>>(S, xprev);
        k_gemm<0, 0><<<dim3(152, 2), 256, SMEM>>>(bg0);
        k_cheby<1, true, 0><<<BATCH, 256>>>(S, xprev);
        k_gemm<1, 0><<<dim3(152, 1), 256, SMEM>>>(bc0);

        k_cheby<128, false, 1><<<BATCH, 256>>>(S, nullptr);
        k_gemm<0, 1><<<dim3(152, 2), 256, SMEM>>>(bg1);
        k_cheby<128, true, 1><<<BATCH, 256>>>(S, nullptr);
        k_gemm<1, 1><<<dim3(152, 1), 256, SMEM>>>(bc1);

        k_proj<<<ROWS / 8, 256>>>(Wp, bp, out + (size_t)t * ROWS);
    }
}

// round 6
// speedup vs baseline: 2.0423x; 1.1245x over previous
#include <cuda_runtime.h>
#include <cuda_bf16.h>
#include <math.h>
#include <stdint.h>

// DCGRU decoder: SEQ=32, B=1024, N=19, H=128, OUT=1, K=2 Chebyshev, 2 layers.
// R6: mma.sync bf16 3-pass + 2 CTAs/SM, h-only cand cheby, fused projection.

#define BATCH 1024
#define NNODE 19
#define HID   128
#define ROWS  (BATCH * NNODE)   // 19456 = 152 * 128
#define SEQLEN 32

#define KP0 448                  // 387 padded to mult of 32
#define K0R 387
#define KP1 768

#define WO_G0 0
#define WO_C0 (WO_G0 + 256 * KP0)
#define WO_G1 (WO_C0 + 128 * KP0)
#define WO_C1 (WO_G1 + 256 * KP1)
#define WTOT  (WO_C1 + 128 * KP1)

// ---------------- persistent device scratch ---------------------------------
__device__ float g_h0[ROWS * HID];
__device__ float g_h1[ROWS * HID];
__device__ float g_ru[ROWS * 256];
__device__ float g_S2[NNODE * NNODE];
__device__ __align__(16) __nv_bfloat16 g_X0h[ROWS * KP0];
__device__ __align__(16) __nv_bfloat16 g_X0l[ROWS * KP0];
__device__ __align__(16) __nv_bfloat16 g_X1h[ROWS * KP1];
__device__ __align__(16) __nv_bfloat16 g_X1l[ROWS * KP1];
__device__ __align__(16) __nv_bfloat16 g_Wh[WTOT];
__device__ __align__(16) __nv_bfloat16 g_Wl[WTOT];

// ---------------- helpers ----------------------------------------------------
__device__ __forceinline__ uint32_t smem_u32(const void* p) {
    uint32_t a;
    asm("{ .reg .u64 t; cvta.to.shared.u64 t, %1; cvt.u32.u64 %0, t; }" : "=r"(a) : "l"(p));
    return a;
}
__device__ __forceinline__ void cpasync16(uint32_t dst, const void* src) {
    asm volatile("cp.async.cg.shared.global [%0], [%1], 16;" :: "r"(dst), "l"(src) : "memory");
}
#define CP_COMMIT() asm volatile("cp.async.commit_group;" ::: "memory")
#define CP_WAIT(n)  asm volatile("cp.async.wait_group %0;" :: "n"(n) : "memory")

__device__ __forceinline__ void ldsm_x4(uint32_t* r, uint32_t addr) {
    asm volatile("ldmatrix.sync.aligned.m8n8.x4.shared.b16 {%0,%1,%2,%3}, [%4];"
                 : "=r"(r[0]), "=r"(r[1]), "=r"(r[2]), "=r"(r[3]) : "r"(addr));
}
__device__ __forceinline__ void mma_bf16(float* d, const uint32_t* a, const uint32_t* b) {
    asm volatile("mma.sync.aligned.m16n8k16.row.col.f32.bf16.bf16.f32 "
                 "{%0,%1,%2,%3},{%4,%5,%6,%7},{%8,%9},{%0,%1,%2,%3};"
                 : "+f"(d[0]), "+f"(d[1]), "+f"(d[2]), "+f"(d[3])
                 : "r"(a[0]), "r"(a[1]), "r"(a[2]), "r"(a[3]), "r"(b[0]), "r"(b[1]));
}
__device__ __forceinline__ void sthl(__nv_bfloat16* H, __nv_bfloat16* L, size_t i, float v) {
    __nv_bfloat16 h = __float2bfloat16(v);
    H[i] = h;
    L[i] = __float2bfloat16(v - __bfloat162float(h));
}

// ---------------- init kernels -----------------------------------------------
__global__ void k_init_h(const float* __restrict__ ih) {
    int i = blockIdx.x * blockDim.x + threadIdx.x;
    if (i < ROWS * HID) { g_h0[i] = ih[i]; g_h1[i] = ih[ROWS * HID + i]; }
}
__global__ void k_zpad() {
    int i = blockIdx.x * blockDim.x + threadIdx.x;
    if (i < ROWS * (KP0 - K0R)) {
        int row = i / (KP0 - K0R), c = K0R + i % (KP0 - K0R);
        g_X0h[(size_t)row * KP0 + c] = __float2bfloat16(0.f);
        g_X0l[(size_t)row * KP0 + c] = __float2bfloat16(0.f);
    }
}
__global__ void k_s2(const float* __restrict__ S) {
    int i = threadIdx.x;
    if (i < NNODE * NNODE) {
        int m = i / NNODE, n = i % NNODE;
        float acc = 0.f;
        for (int k = 0; k < NNODE; k++) acc += S[m * NNODE + k] * S[k * NNODE + n];
        g_S2[i] = 2.f * acc - (m == n ? 1.f : 0.f);
    }
}
__global__ void k_prepw(const float* __restrict__ W, int off, int K, int KP_, int Nw) {
    int i = blockIdx.x * blockDim.x + threadIdx.x;
    if (i >= Nw * KP_) return;
    int n = i / KP_, k = i % KP_;
    float w = (k < K) ? W[k * Nw + n] : 0.f;
    __nv_bfloat16 h = __float2bfloat16(w);
    g_Wh[off + i] = h;
    g_Wl[off + i] = __float2bfloat16(w - __bfloat162float(h));
}

// ---------------- fused concat + Chebyshev -> bf16 hi/lo planes --------------
// CAND=true processes only the h-part features (x-part columns in g_X are
// unchanged since the gate pass; x and h features never mix in the diffusion).
template <int FIN, bool CAND, int LAYER>
__global__ void k_cheby(const float* __restrict__ S, const float* __restrict__ xprev) {
    constexpr int F  = FIN + HID;
    constexpr int FW = CAND ? HID : F;      // features handled this pass
    constexpr int STR = LAYER ? KP1 : KP0;
    __shared__ float s_src[NNODE][FW];
    __shared__ float sS[NNODE * NNODE], sS2[NNODE * NNODE];

    const int b = blockIdx.x, tid = threadIdx.x;
    __nv_bfloat16* Xh = LAYER ? g_X1h : g_X0h;
    __nv_bfloat16* Xl = LAYER ? g_X1l : g_X0l;

    for (int i = tid; i < NNODE * NNODE; i += 256) { sS[i] = S[i]; sS2[i] = g_S2[i]; }

    for (int i = tid; i < NNODE * FW; i += 256) {
        int n = i / FW, f = i % FW;
        int row = b * NNODE + n;
        float v;
        if (CAND) {
            v = (LAYER ? g_h1 : g_h0)[(size_t)row * HID + f] *
                g_ru[(size_t)row * 256 + f];
        } else if (f < FIN) {
            if (FIN == 1) v = xprev ? xprev[row] : 0.f;
            else          v = g_h0[(size_t)row * HID + f];
        } else {
            v = (LAYER ? g_h1 : g_h0)[(size_t)row * HID + (f - FIN)];
        }
        s_src[n][f] = v;
    }
    __syncthreads();

    const int cofs = CAND ? FIN : 0;
    for (int p = tid; p < NNODE * FW; p += 256) {
        int f = p % FW, m = p / FW;
        float x0 = s_src[m][f], a1 = 0.f, a2 = 0.f;
#pragma unroll
        for (int n = 0; n < NNODE; n++) {
            float v = s_src[n][f];
            a1 = fmaf(sS[m * NNODE + n], v, a1);
            a2 = fmaf(sS2[m * NNODE + n], v, a2);
        }
        size_t base = (size_t)(b * NNODE + m) * STR + cofs;
        sthl(Xh, Xl, base + f,         x0);
        sthl(Xh, Xl, base + F + f,     a1);
        sthl(Xh, Xl, base + 2 * F + f, a2);
    }
}

// ---------------- bf16 mma.sync GEMM (2 CTAs/SM) -----------------------------
// BM=128, BN=128, BK=32; 8 warps 4(m)x2(n), warp tile 32x64; RPAD=40 -> LDSM
// conflict-free. MODE 0: g_ru=sigmoid(.)  MODE 1: h=u*h+(1-u)*tanh(.)
// PROJ: additionally out[row] = h1[row,:].Wp + bp (smem reduction).
#define RPAD 40
#define PLANEH (128 * RPAD)
#define STAGEB (4 * PLANEH * 2)

template <int MODE, int LAYER, bool PROJ>
__global__ void __launch_bounds__(256, 2)
k_gemm(const float* __restrict__ bias, const float* __restrict__ Wp,
       const float* __restrict__ bp, float* __restrict__ outp) {
    constexpr int KP = LAYER ? KP1 : KP0;
    constexpr int NT = KP / 32;

    extern __shared__ __align__(16) char smem[];
    const uint32_t sbase = smem_u32(smem);

    const int tid = threadIdx.x, wid = tid >> 5, lane = tid & 31;
    const int row0 = blockIdx.x * 128;
    const int col0 = blockIdx.y * 128;
    const int wm = (wid & 3) * 32, wn = (wid >> 2) * 64;
    const int gr = lane >> 2, gc = lane & 3;

    const __nv_bfloat16* Xh = LAYER ? g_X1h : g_X0h;
    const __nv_bfloat16* Xl = LAYER ? g_X1l : g_X0l;
    const int woff = (MODE == 0) ? (LAYER ? WO_G1 : WO_G0) : (LAYER ? WO_C1 : WO_C0);
    const __nv_bfloat16* Wh = g_Wh + woff;
    const __nv_bfloat16* Wl = g_Wl + woff;

    auto load_stage = [&](int kt, int s) {
        const uint32_t stg = sbase + s * STAGEB;
#pragma unroll
        for (int i = 0; i < 8; i++) {
            int slot = tid + i * 256;            // 0..2047
            int pl   = slot >> 9;                // Ah, Al, Bh, Bl
            int e    = slot & 511;
            int r    = e >> 2;
            int kq   = (e & 3) * 8;
            uint32_t dst = stg + (uint32_t)pl * (PLANEH * 2) + (uint32_t)(r * RPAD + kq) * 2;
            const __nv_bfloat16* src;
            if (pl == 0)      src = Xh + (size_t)(row0 + r) * KP + kt * 32 + kq;
            else if (pl == 1) src = Xl + (size_t)(row0 + r) * KP + kt * 32 + kq;
            else if (pl == 2) src = Wh + (size_t)(col0 + r) * KP + kt * 32 + kq;
            else              src = Wl + (size_t)(col0 + r) * KP + kt * 32 + kq;
            cpasync16(dst, src);
        }
        CP_COMMIT();
    };

    float acc[2][8][4];
#pragma unroll
    for (int i = 0; i < 2; i++)
#pragma unroll
        for (int j = 0; j < 8; j++)
#pragma unroll
            for (int q = 0; q < 4; q++) acc[i][j][q] = 0.f;

    load_stage(0, 0);

    const int a_r = lane & 15, a_k = (lane >> 4) * 8;
    const int b_r = (lane & 7) + ((lane >> 4) << 3), b_k = ((lane >> 3) & 1) * 8;

    for (int kt = 0; kt < NT; kt++) {
        const int s = kt & 1;
        if (kt + 1 < NT) load_stage(kt + 1, s ^ 1);
        if (kt + 1 < NT) { CP_WAIT(1); } else { CP_WAIT(0); }
        __syncthreads();

        const uint32_t stg = sbase + s * STAGEB;
        const uint32_t sAh = stg;
        const uint32_t sAl = stg + PLANEH * 2;
        const uint32_t sBh = stg + 2 * PLANEH * 2;
        const uint32_t sBl = stg + 3 * PLANEH * 2;

#pragma unroll
        for (int ks = 0; ks < 32; ks += 16) {
            uint32_t ah[2][4], al[2][4];
#pragma unroll
            for (int mi = 0; mi < 2; mi++) {
                uint32_t off = (uint32_t)((wm + mi * 16 + a_r) * RPAD + ks + a_k) * 2;
                ldsm_x4(ah[mi], sAh + off);
                ldsm_x4(al[mi], sAl + off);
            }
#pragma unroll
            for (int nq = 0; nq < 4; nq++) {
                uint32_t bh[4], bl[4];
                uint32_t off = (uint32_t)((wn + nq * 16 + b_r) * RPAD + ks + b_k) * 2;
                ldsm_x4(bh, sBh + off);
                ldsm_x4(bl, sBl + off);
#pragma unroll
                for (int half = 0; half < 2; half++) {
                    int ni = nq * 2 + half;
                    const uint32_t* pbh = &bh[half * 2];
                    const uint32_t* pbl = &bl[half * 2];
#pragma unroll
                    for (int mi = 0; mi < 2; mi++) {
                        mma_bf16(acc[mi][ni], ah[mi], pbh);
                        mma_bf16(acc[mi][ni], al[mi], pbh);
                        mma_bf16(acc[mi][ni], ah[mi], pbl);
                    }
                }
            }
        }
        __syncthreads();
    }

    // ---------------- epilogue ----------------
    float* hbuf = LAYER ? g_h1 : g_h0;
    float* red = (float*)smem;
    float pr[2][2] = {{0.f, 0.f}, {0.f, 0.f}};   // proj partials [mi][rr]
    if (PROJ) {
        if (tid < 128) red[tid] = 0.f;
        __syncthreads();
    }
#pragma unroll
    for (int mi = 0; mi < 2; mi++) {
#pragma unroll
        for (int ni = 0; ni < 8; ni++) {
            int r0 = row0 + wm + mi * 16 + gr;
            int c  = col0 + wn + ni * 8 + gc * 2;
            float b0 = bias[c], b1 = bias[c + 1];
            float* pa = acc[mi][ni];
            if (MODE == 0) {
                float2 v0, v1;
                v0.x = 1.f / (1.f + expf(-(pa[0] + b0)));
                v0.y = 1.f / (1.f + expf(-(pa[1] + b1)));
                v1.x = 1.f / (1.f + expf(-(pa[2] + b0)));
                v1.y = 1.f / (1.f + expf(-(pa[3] + b1)));
                *(float2*)(&g_ru[(size_t)r0 * 256 + c])       = v0;
                *(float2*)(&g_ru[(size_t)(r0 + 8) * 256 + c]) = v1;
            } else {
#pragma unroll
                for (int rr = 0; rr < 2; rr++) {
                    int r = r0 + rr * 8;
                    float2 u = *(const float2*)(&g_ru[(size_t)r * 256 + 128 + c]);
                    float2 h = *(const float2*)(&hbuf[(size_t)r * HID + c]);
                    float2 o;
                    o.x = u.x * h.x + (1.f - u.x) * tanhf(pa[rr * 2 + 0] + b0);
                    o.y = u.y * h.y + (1.f - u.y) * tanhf(pa[rr * 2 + 1] + b1);
                    *(float2*)(&hbuf[(size_t)r * HID + c]) = o;
                    if (PROJ)
                        pr[mi][rr] += o.x * Wp[c] + o.y * Wp[c + 1];
                }
            }
        }
    }
    if (PROJ) {
#pragma unroll
        for (int mi = 0; mi < 2; mi++)
#pragma unroll
            for (int rr = 0; rr < 2; rr++)
                atomicAdd(&red[wm + mi * 16 + gr + rr * 8], pr[mi][rr]);
        __syncthreads();
        if (tid < 128) outp[row0 + tid] = red[tid] + bp[0];
    }
}

// ---------------- launch -----------------------------------------------------
extern "C" void kernel_launch(void* const* d_in, const int* in_sizes, int n_in,
                              void* d_out, int out_size) {
    (void)in_sizes; (void)n_in; (void)out_size;
    const float* ih  = (const float*)d_in[1];
    const float* S   = (const float*)d_in[2];
    const float* Wg0 = (const float*)d_in[3];
    const float* bg0 = (const float*)d_in[4];
    const float* Wc0 = (const float*)d_in[5];
    const float* bc0 = (const float*)d_in[6];
    const float* Wg1 = (const float*)d_in[7];
    const float* bg1 = (const float*)d_in[8];
    const float* Wc1 = (const float*)d_in[9];
    const float* bc1 = (const float*)d_in[10];
    const float* Wp  = (const float*)d_in[11];
    const float* bp  = (const float*)d_in[12];
    float* out = (float*)d_out;

    const int SMEM = 2 * STAGEB;   // 81920 B -> 2 CTAs/SM
    cudaFuncSetAttribute((const void*)k_gemm<0, 0, false>, cudaFuncAttributeMaxDynamicSharedMemorySize, SMEM);
    cudaFuncSetAttribute((const void*)k_gemm<0, 1, false>, cudaFuncAttributeMaxDynamicSharedMemorySize, SMEM);
    cudaFuncSetAttribute((const void*)k_gemm<1, 0, false>, cudaFuncAttributeMaxDynamicSharedMemorySize, SMEM);
    cudaFuncSetAttribute((const void*)k_gemm<1, 1, true>,  cudaFuncAttributeMaxDynamicSharedMemorySize, SMEM);

    k_init_h<<<(ROWS * HID + 255) / 256, 256>>>(ih);
    k_zpad<<<(ROWS * (KP0 - K0R) + 255) / 256, 256>>>();
    k_s2<<<1, 384>>>(S);
    k_prepw<<<(256 * KP0 + 255) / 256, 256>>>(Wg0, WO_G0, K0R, KP0, 256);
    k_prepw<<<(128 * KP0 + 255) / 256, 256>>>(Wc0, WO_C0, K0R, KP0, 128);
    k_prepw<<<(256 * KP1 + 255) / 256, 256>>>(Wg1, WO_G1, 768, KP1, 256);
    k_prepw<<<(128 * KP1 + 255) / 256, 256>>>(Wc1, WO_C1, 768, KP1, 128);

    for (int t = 0; t < SEQLEN; t++) {
        const float* xprev = t ? out + (size_t)(t - 1) * ROWS : nullptr;
        float* out_t = out + (size_t)t * ROWS;

        k_cheby<1, false, 0><<<BATCH, 256>>>(S, xprev);
        k_gemm<0, 0, false><<<dim3(152, 2), 256, SMEM>>>(bg0, nullptr, nullptr, nullptr);
        k_cheby<1, true, 0><<<BATCH, 256>>>(S, xprev);
        k_gemm<1, 0, false><<<dim3(152, 1), 256, SMEM>>>(bc0, nullptr, nullptr, nullptr);

        k_cheby<128, false, 1><<<BATCH, 256>>>(S, nullptr);
        k_gemm<0, 1, false><<<dim3(152, 2), 256, SMEM>>>(bg1, nullptr, nullptr, nullptr);
        k_cheby<128, true, 1><<<BATCH, 256>>>(S, nullptr);
        k_gemm<1, 1, true><<<dim3(152, 1), 256, SMEM>>>(bc1, Wp, bp, out_t);
    }
}

// round 7
// speedup vs baseline: 2.6679x; 1.3063x over previous
#include <cuda_runtime.h>
#include <cuda_bf16.h>
#include <math.h>
#include <stdint.h>

// DCGRU decoder: SEQ=32, B=1024, N=19, H=128, OUT=1, K=2 Chebyshev, 2 layers.
// R7: BM64 swizzled-smem mma.sync GEMM (4 CTAs/SM), KP0=416 permuted layout,
//     vectorized bf16x2 cheby, r*h fused into gate epilogue.

#define BATCH 1024
#define NNODE 19
#define HID   128
#define ROWS  (BATCH * NNODE)   // 19456 = 304 * 64
#define SEQLEN 32

#define KP0 416                  // layer0 K: [h*3 (384) | x0 x1 x2 | pad] = 416
#define K0R 387
#define KP1 768                  // layer1 K: [x|h] * 3

#define WO_G0 0
#define WO_C0 (WO_G0 + 256 * KP0)
#define WO_G1 (WO_C0 + 128 * KP0)
#define WO_C1 (WO_G1 + 256 * KP1)
#define WTOT  (WO_C1 + 128 * KP1)

// ---------------- persistent device scratch ---------------------------------
__device__ float g_h0[ROWS * HID];
__device__ float g_h1[ROWS * HID];
__device__ float g_ru[ROWS * 256];          // [r*h | u]
__device__ float g_S2[NNODE * NNODE];
__device__ __align__(16) __nv_bfloat16 g_X0h[ROWS * KP0];
__device__ __align__(16) __nv_bfloat16 g_X0l[ROWS * KP0];
__device__ __align__(16) __nv_bfloat16 g_X1h[ROWS * KP1];
__device__ __align__(16) __nv_bfloat16 g_X1l[ROWS * KP1];
__device__ __align__(16) __nv_bfloat16 g_Wh[WTOT];
__device__ __align__(16) __nv_bfloat16 g_Wl[WTOT];

// ---------------- helpers ----------------------------------------------------
__device__ __forceinline__ uint32_t smem_u32(const void* p) {
    uint32_t a;
    asm("{ .reg .u64 t; cvta.to.shared.u64 t, %1; cvt.u32.u64 %0, t; }" : "=r"(a) : "l"(p));
    return a;
}
__device__ __forceinline__ void cpasync16(uint32_t dst, const void* src) {
    asm volatile("cp.async.cg.shared.global [%0], [%1], 16;" :: "r"(dst), "l"(src) : "memory");
}
#define CP_COMMIT() asm volatile("cp.async.commit_group;" ::: "memory")
#define CP_WAIT(n)  asm volatile("cp.async.wait_group %0;" :: "n"(n) : "memory")

__device__ __forceinline__ void ldsm_x4(uint32_t* r, uint32_t addr) {
    asm volatile("ldmatrix.sync.aligned.m8n8.x4.shared.b16 {%0,%1,%2,%3}, [%4];"
                 : "=r"(r[0]), "=r"(r[1]), "=r"(r[2]), "=r"(r[3]) : "r"(addr));
}
__device__ __forceinline__ void mma_bf16(float* d, const uint32_t* a, const uint32_t* b) {
    asm volatile("mma.sync.aligned.m16n8k16.row.col.f32.bf16.bf16.f32 "
                 "{%0,%1,%2,%3},{%4,%5,%6,%7},{%8,%9},{%0,%1,%2,%3};"
                 : "+f"(d[0]), "+f"(d[1]), "+f"(d[2]), "+f"(d[3])
                 : "r"(a[0]), "r"(a[1]), "r"(a[2]), "r"(a[3]), "r"(b[0]), "r"(b[1]));
}
__device__ __forceinline__ uint32_t swz64(uint32_t o) { return o ^ ((o >> 3) & 0x30); }

__device__ __forceinline__ void store2(__nv_bfloat16* __restrict__ H,
                                       __nv_bfloat16* __restrict__ L,
                                       size_t idx, float2 v) {
    __nv_bfloat162 h2 = __float22bfloat162_rn(v);
    *(__nv_bfloat162*)(H + idx) = h2;
    float2 hf = __bfloat1622float2(h2);
    __nv_bfloat162 l2 = __float22bfloat162_rn(make_float2(v.x - hf.x, v.y - hf.y));
    *(__nv_bfloat162*)(L + idx) = l2;
}
__device__ __forceinline__ void store1(__nv_bfloat16* H, __nv_bfloat16* L,
                                       size_t idx, float v) {
    __nv_bfloat16 h = __float2bfloat16(v);
    H[idx] = h;
    L[idx] = __float2bfloat16(v - __bfloat162float(h));
}

// ---------------- init kernels -----------------------------------------------
__global__ void k_init_h(const float* __restrict__ ih) {
    int i = blockIdx.x * blockDim.x + threadIdx.x;
    if (i < ROWS * HID) { g_h0[i] = ih[i]; g_h1[i] = ih[ROWS * HID + i]; }
}
__global__ void k_zpad() {   // zero X0 K-pad cols [387,416)
    int i = blockIdx.x * blockDim.x + threadIdx.x;
    const int PC = KP0 - K0R;
    if (i < ROWS * PC) {
        int row = i / PC, c = K0R + i % PC;
        g_X0h[(size_t)row * KP0 + c] = __float2bfloat16(0.f);
        g_X0l[(size_t)row * KP0 + c] = __float2bfloat16(0.f);
    }
}
__global__ void k_s2(const float* __restrict__ S) {
    int i = threadIdx.x;
    if (i < NNODE * NNODE) {
        int m = i / NNODE, n = i % NNODE;
        float acc = 0.f;
        for (int k = 0; k < NNODE; k++) acc += S[m * NNODE + k] * S[k * NNODE + n];
        g_S2[i] = 2.f * acc - (m == n ? 1.f : 0.f);
    }
}
// weights: out[n*KP + kk] = W[refrow(kk)*Nw + n], hi/lo split.
// PERM (layer0): kk<384 -> j=kk/128, i=kk%128, ref = j*129+1+i;
//                kk in [384,387) -> ref = (kk-384)*129;  kk>=387 -> zero.
template <bool PERM>
__global__ void k_prepw(const float* __restrict__ W, int off, int K, int KP_, int Nw) {
    int i = blockIdx.x * blockDim.x + threadIdx.x;
    if (i >= Nw * KP_) return;
    int n = i / KP_, kk = i % KP_;
    float w;
    if (PERM) {
        if (kk < 384)       w = W[((kk >> 7) * 129 + 1 + (kk & 127)) * Nw + n];
        else if (kk < 387)  w = W[(kk - 384) * 129 * Nw + n];
        else                w = 0.f;
    } else {
        w = (kk < K) ? W[kk * Nw + n] : 0.f;
    }
    __nv_bfloat16 h = __float2bfloat16(w);
    g_Wh[off + i] = h;
    g_Wl[off + i] = __float2bfloat16(w - __bfloat162float(h));
}

// ---------------- cheby kernels (vectorized) ---------------------------------
// layer0 gate: h feats -> cols j*128 + f (j=0..2), x feats -> 384+j.
__global__ void k_cheby0_gate(const float* __restrict__ S, const float* __restrict__ xprev) {
    __shared__ float2 s2[NNODE][64];
    __shared__ float sx[NNODE];
    __shared__ float sS[361], sS2[361];
    const int b = blockIdx.x, tid = threadIdx.x;

    for (int i = tid; i < 361; i += 256) { sS[i] = S[i]; sS2[i] = g_S2[i]; }
    for (int i = tid; i < NNODE * 64; i += 256) {
        int n = i >> 6, f2 = i & 63;
        s2[n][f2] = *(const float2*)(g_h0 + (size_t)(b * NNODE + n) * HID + 2 * f2);
    }
    if (tid < NNODE) sx[tid] = xprev ? xprev[b * NNODE + tid] : 0.f;
    __syncthreads();

    for (int p = tid; p < NNODE * 64; p += 256) {
        int m = p >> 6, f2 = p & 63;
        float2 x0 = s2[m][f2];
        float2 a1 = make_float2(0.f, 0.f), a2 = make_float2(0.f, 0.f);
#pragma unroll
        for (int n = 0; n < NNODE; n++) {
            float2 v = s2[n][f2];
            float w1 = sS[m * NNODE + n], w2 = sS2[m * NNODE + n];
            a1.x = fmaf(w1, v.x, a1.x); a1.y = fmaf(w1, v.y, a1.y);
            a2.x = fmaf(w2, v.x, a2.x); a2.y = fmaf(w2, v.y, a2.y);
        }
        size_t base = (size_t)(b * NNODE + m) * KP0 + 2 * f2;
        store2(g_X0h, g_X0l, base,       x0);
        store2(g_X0h, g_X0l, base + 128, a1);
        store2(g_X0h, g_X0l, base + 256, a2);
    }
    if (tid < NNODE) {
        int m = tid;
        float x0 = sx[m], a1 = 0.f, a2 = 0.f;
#pragma unroll
        for (int n = 0; n < NNODE; n++) {
            a1 = fmaf(sS[m * NNODE + n], sx[n], a1);
            a2 = fmaf(sS2[m * NNODE + n], sx[n], a2);
        }
        size_t base = (size_t)(b * NNODE + m) * KP0 + 384;
        store1(g_X0h, g_X0l, base, x0);
        store1(g_X0h, g_X0l, base + 1, a1);
        store1(g_X0h, g_X0l, base + 2, a2);
    }
}

// layer1 gate: src [h0 | h1] (256 feats) -> cols j*256 + f.
__global__ void k_cheby1_gate(const float* __restrict__ S) {
    __shared__ float2 s2[NNODE][128];
    __shared__ float sS[361], sS2[361];
    const int b = blockIdx.x, tid = threadIdx.x;

    for (int i = tid; i < 361; i += 256) { sS[i] = S[i]; sS2[i] = g_S2[i]; }
    for (int i = tid; i < NNODE * 128; i += 256) {
        int n = i >> 7, f2 = i & 127;
        size_t row = (size_t)(b * NNODE + n);
        s2[n][f2] = (f2 < 64)
            ? *(const float2*)(g_h0 + row * HID + 2 * f2)
            : *(const float2*)(g_h1 + row * HID + 2 * (f2 - 64));
    }
    __syncthreads();

    for (int p = tid; p < NNODE * 128; p += 256) {
        int m = p >> 7, f2 = p & 127;
        float2 x0 = s2[m][f2];
        float2 a1 = make_float2(0.f, 0.f), a2 = make_float2(0.f, 0.f);
#pragma unroll
        for (int n = 0; n < NNODE; n++) {
            float2 v = s2[n][f2];
            float w1 = sS[m * NNODE + n], w2 = sS2[m * NNODE + n];
            a1.x = fmaf(w1, v.x, a1.x); a1.y = fmaf(w1, v.y, a1.y);
            a2.x = fmaf(w2, v.x, a2.x); a2.y = fmaf(w2, v.y, a2.y);
        }
        size_t base = (size_t)(b * NNODE + m) * KP1 + 2 * f2;
        store2(g_X1h, g_X1l, base,       x0);
        store2(g_X1h, g_X1l, base + 256, a1);
        store2(g_X1h, g_X1l, base + 512, a2);
    }
}

// cand cheby: src r*h (g_ru cols 0..127). LAYER0 -> cols j*128+f of X0;
// LAYER1 -> cols j*256+128+f of X1 (x part untouched).
template <int LAYER>
__global__ void k_cheby_cand(const float* __restrict__ S) {
    __shared__ float2 s2[NNODE][64];
    __shared__ float sS[361], sS2[361];
    const int b = blockIdx.x, tid = threadIdx.x;
    __nv_bfloat16* Xh = LAYER ? g_X1h : g_X0h;
    __nv_bfloat16* Xl = LAYER ? g_X1l : g_X0l;
    constexpr int STR  = LAYER ? KP1 : KP0;
    constexpr int JSTR = LAYER ? 256 : 128;
    constexpr int COFS = LAYER ? 128 : 0;

    for (int i = tid; i < 361; i += 256) { sS[i] = S[i]; sS2[i] = g_S2[i]; }
    for (int i = tid; i < NNODE * 64; i += 256) {
        int n = i >> 6, f2 = i & 63;
        s2[n][f2] = *(const float2*)(g_ru + (size_t)(b * NNODE + n) * 256 + 2 * f2);
    }
    __syncthreads();

    for (int p = tid; p < NNODE * 64; p += 256) {
        int m = p >> 6, f2 = p & 63;
        float2 x0 = s2[m][f2];
        float2 a1 = make_float2(0.f, 0.f), a2 = make_float2(0.f, 0.f);
#pragma unroll
        for (int n = 0; n < NNODE; n++) {
            float2 v = s2[n][f2];
            float w1 = sS[m * NNODE + n], w2 = sS2[m * NNODE + n];
            a1.x = fmaf(w1, v.x, a1.x); a1.y = fmaf(w1, v.y, a1.y);
            a2.x = fmaf(w2, v.x, a2.x); a2.y = fmaf(w2, v.y, a2.y);
        }
        size_t base = (size_t)(b * NNODE + m) * STR + COFS + 2 * f2;
        store2(Xh, Xl, base,            x0);
        store2(Xh, Xl, base + JSTR,     a1);
        store2(Xh, Xl, base + 2 * JSTR, a2);
    }
}

// ---------------- bf16 mma.sync GEMM, BM=64 BN=128 BK=32 ---------------------
// 128 threads, 4 warps (2m x 2n), warp tile 32x64. Swizzled smem (SW64),
// 2-stage cp.async, 4 CTAs/SM. 3-pass split: AhWh + AlWh + AhWl.
// MODE 0 gate: g_ru = sigmoid(.) (cols<128 store r*h). MODE 1 cand: GRU update.
#define STAGEB 24576   // Ah 4K | Al 4K | Bh 8K | Bl 8K

template <int MODE, int LAYER, bool PROJ>
__global__ void __launch_bounds__(128, 4)
k_gemm(const float* __restrict__ bias, const float* __restrict__ Wp,
       const float* __restrict__ bp, float* __restrict__ outp) {
    constexpr int KP = LAYER ? KP1 : KP0;
    constexpr int NT = KP / 32;

    extern __shared__ __align__(16) char smem[];
    const uint32_t sbase = smem_u32(smem);

    const int tid = threadIdx.x, wid = tid >> 5, lane = tid & 31;
    const int row0 = blockIdx.x * 64;
    const int col0 = blockIdx.y * 128;
    const int wm = (wid & 1) * 32, wn = (wid >> 1) * 64;
    const int gr = lane >> 2, gc = lane & 3;

    const __nv_bfloat16* Xh = LAYER ? g_X1h : g_X0h;
    const __nv_bfloat16* Xl = LAYER ? g_X1l : g_X0l;
    const int woff = (MODE == 0) ? (LAYER ? WO_G1 : WO_G0) : (LAYER ? WO_C1 : WO_C0);
    const __nv_bfloat16* Wh = g_Wh + woff;
    const __nv_bfloat16* Wl = g_Wl + woff;

    auto load_stage = [&](int kt, int s) {
        const uint32_t stg = sbase + s * STAGEB;
#pragma unroll
        for (int i = 0; i < 12; i++) {
            int slot = tid + i * 128;            // 0..1535
            uint32_t dst;
            const __nv_bfloat16* src;
            if (slot < 512) {                    // A planes: 2 x 64 rows x 4 chunks
                int pl = slot >> 8, e = slot & 255;
                int r = e >> 2, c16 = e & 3;
                dst = stg + pl * 4096u + swz64(r * 64 + c16 * 16);
                src = (pl ? Xl : Xh) + (size_t)(row0 + r) * KP + kt * 32 + c16 * 8;
            } else {                             // B planes: 2 x 128 rows x 4 chunks
                int t2 = slot - 512;
                int pl = t2 >> 9, e = t2 & 511;
                int r = e >> 2, c16 = e & 3;
                dst = stg + 8192u + pl * 8192u + swz64(r * 64 + c16 * 16);
                src = (pl ? Wl : Wh) + (size_t)(col0 + r) * KP + kt * 32 + c16 * 8;
            }
            cpasync16(dst, src);
        }
        CP_COMMIT();
    };

    float acc[2][8][4];
#pragma unroll
    for (int i = 0; i < 2; i++)
#pragma unroll
        for (int j = 0; j < 8; j++)
#pragma unroll
            for (int q = 0; q < 4; q++) acc[i][j][q] = 0.f;

    load_stage(0, 0);

    const int a_r = lane & 15, a_k = (lane >> 4) * 8;
    const int b_r = (lane & 7) + ((lane >> 4) << 3), b_k = ((lane >> 3) & 1) * 8;

    for (int kt = 0; kt < NT; kt++) {
        const int s = kt & 1;
        if (kt + 1 < NT) load_stage(kt + 1, s ^ 1);
        if (kt + 1 < NT) { CP_WAIT(1); } else { CP_WAIT(0); }
        __syncthreads();

        const uint32_t stg = sbase + s * STAGEB;
        const uint32_t sAh = stg, sAl = stg + 4096;
        const uint32_t sBh = stg + 8192, sBl = stg + 16384;

#pragma unroll
        for (int ks = 0; ks < 32; ks += 16) {
            uint32_t ah[2][4], al[2][4];
#pragma unroll
            for (int mi = 0; mi < 2; mi++) {
                uint32_t off = swz64((uint32_t)((wm + mi * 16 + a_r) * 64 + (ks + a_k) * 2));
                ldsm_x4(ah[mi], sAh + off);
                ldsm_x4(al[mi], sAl + off);
            }
#pragma unroll
            for (int nq = 0; nq < 4; nq++) {
                uint32_t bh[4], bl[4];
                uint32_t off = swz64((uint32_t)((wn + nq * 16 + b_r) * 64 + (ks + b_k) * 2));
                ldsm_x4(bh, sBh + off);
                ldsm_x4(bl, sBl + off);
#pragma unroll
                for (int half = 0; half < 2; half++) {
                    int ni = nq * 2 + half;
                    const uint32_t* pbh = &bh[half * 2];
                    const uint32_t* pbl = &bl[half * 2];
#pragma unroll
                    for (int mi = 0; mi < 2; mi++) {
                        mma_bf16(acc[mi][ni], ah[mi], pbh);
                        mma_bf16(acc[mi][ni], al[mi], pbh);
                        mma_bf16(acc[mi][ni], ah[mi], pbl);
                    }
                }
            }
        }
        __syncthreads();
    }

    // ---------------- epilogue ----------------
    float* hbuf = LAYER ? g_h1 : g_h0;
    float* red = (float*)smem;
    float pr[2][2] = {{0.f, 0.f}, {0.f, 0.f}};
    if (PROJ) {
        if (tid < 64) red[tid] = 0.f;
        __syncthreads();
    }
#pragma unroll
    for (int mi = 0; mi < 2; mi++) {
#pragma unroll
        for (int ni = 0; ni < 8; ni++) {
            int r0 = row0 + wm + mi * 16 + gr;
            int c  = col0 + wn + ni * 8 + gc * 2;
            float b0 = bias[c], b1 = bias[c + 1];
            float* pa = acc[mi][ni];
            if (MODE == 0) {
#pragma unroll
                for (int rr = 0; rr < 2; rr++) {
                    int r = r0 + rr * 8;
                    float2 v;
                    v.x = 1.f / (1.f + expf(-(pa[rr * 2 + 0] + b0)));
                    v.y = 1.f / (1.f + expf(-(pa[rr * 2 + 1] + b1)));
                    if (col0 == 0) {   // r-columns: store r*h
                        float2 h = *(const float2*)(&hbuf[(size_t)r * HID + c]);
                        v.x *= h.x; v.y *= h.y;
                    }
                    *(float2*)(&g_ru[(size_t)r * 256 + c]) = v;
                }
            } else {
#pragma unroll
                for (int rr = 0; rr < 2; rr++) {
                    int r = r0 + rr * 8;
                    float2 u = *(const float2*)(&g_ru[(size_t)r * 256 + 128 + c]);
                    float2 h = *(const float2*)(&hbuf[(size_t)r * HID + c]);
                    float2 o;
                    o.x = u.x * h.x + (1.f - u.x) * tanhf(pa[rr * 2 + 0] + b0);
                    o.y = u.y * h.y + (1.f - u.y) * tanhf(pa[rr * 2 + 1] + b1);
                    *(float2*)(&hbuf[(size_t)r * HID + c]) = o;
                    if (PROJ)
                        pr[0][rr] += o.x * Wp[c] + o.y * Wp[c + 1];
                }
            }
            if (MODE == 1 && PROJ && ni == 7) {
                // accumulate this mi's partials into smem, reset for next mi
#pragma unroll
                for (int rr = 0; rr < 2; rr++) {
                    atomicAdd(&red[wm + mi * 16 + gr + rr * 8], pr[0][rr]);
                    pr[0][rr] = 0.f;
                }
            }
        }
    }
    if (PROJ) {
        __syncthreads();
        if (tid < 64) outp[row0 + tid] = red[tid] + bp[0];
    }
}

// ---------------- launch -----------------------------------------------------
extern "C" void kernel_launch(void* const* d_in, const int* in_sizes, int n_in,
                              void* d_out, int out_size) {
    (void)in_sizes; (void)n_in; (void)out_size;
    const float* ih  = (const float*)d_in[1];
    const float* S   = (const float*)d_in[2];
    const float* Wg0 = (const float*)d_in[3];
    const float* bg0 = (const float*)d_in[4];
    const float* Wc0 = (const float*)d_in[5];
    const float* bc0 = (const float*)d_in[6];
    const float* Wg1 = (const float*)d_in[7];
    const float* bg1 = (const float*)d_in[8];
    const float* Wc1 = (const float*)d_in[9];
    const float* bc1 = (const float*)d_in[10];
    const float* Wp  = (const float*)d_in[11];
    const float* bp  = (const float*)d_in[12];
    float* out = (float*)d_out;

    const int SMEM = 2 * STAGEB;   // 49152 B -> 4 CTAs/SM
    cudaFuncSetAttribute((const void*)k_gemm<0, 0, false>, cudaFuncAttributeMaxDynamicSharedMemorySize, SMEM);
    cudaFuncSetAttribute((const void*)k_gemm<0, 1, false>, cudaFuncAttributeMaxDynamicSharedMemorySize, SMEM);
    cudaFuncSetAttribute((const void*)k_gemm<1, 0, false>, cudaFuncAttributeMaxDynamicSharedMemorySize, SMEM);
    cudaFuncSetAttribute((const void*)k_gemm<1, 1, true>,  cudaFuncAttributeMaxDynamicSharedMemorySize, SMEM);

    k_init_h<<<(ROWS * HID + 255) / 256, 256>>>(ih);
    k_zpad<<<(ROWS * (KP0 - K0R) + 255) / 256, 256>>>();
    k_s2<<<1, 384>>>(S);
    k_prepw<true ><<<(256 * KP0 + 255) / 256, 256>>>(Wg0, WO_G0, K0R, KP0, 256);
    k_prepw<true ><<<(128 * KP0 + 255) / 256, 256>>>(Wc0, WO_C0, K0R, KP0, 128);
    k_prepw<false><<<(256 * KP1 + 255) / 256, 256>>>(Wg1, WO_G1, 768, KP1, 256);
    k_prepw<false><<<(128 * KP1 + 255) / 256, 256>>>(Wc1, WO_C1, 768, KP1, 128);

    for (int t = 0; t < SEQLEN; t++) {
        const float* xprev = t ? out + (size_t)(t - 1) * ROWS : nullptr;
        float* out_t = out + (size_t)t * ROWS;

        k_cheby0_gate<<<BATCH, 256>>>(S, xprev);
        k_gemm<0, 0, false><<<dim3(304, 2), 128, SMEM>>>(bg0, nullptr, nullptr, nullptr);
        k_cheby_cand<0><<<BATCH, 256>>>(S);
        k_gemm<1, 0, false><<<dim3(304, 1), 128, SMEM>>>(bc0, nullptr, nullptr, nullptr);

        k_cheby1_gate<<<BATCH, 256>>>(S);
        k_gemm<0, 1, false><<<dim3(304, 2), 128, SMEM>>>(bg1, nullptr, nullptr, nullptr);
        k_cheby_cand<1><<<BATCH, 256>>>(S);
        k_gemm<1, 1, true><<<dim3(304, 1), 128, SMEM>>>(bc1, Wp, bp, out_t);
    }
}